// round 12
// baseline (speedup 1.0000x reference)
#include <cuda_runtime.h>

// SPU transformer bound propagation: elementwise over N=8192 rows (320 KB).
// Best config: grid 32 x block 128, float4 = 2 rows/thread, guard-free exact
// grid, HW-tanh sigmoid: sigmoid(-x)-1 = -0.5 - 0.5*tanh(x/2).
// This round: all 4 MUFU.TANH + both RCPs batched up front so their latencies
// overlap across the two row pipelines. rel_err ~4e-7 << 1e-3.

__device__ __forceinline__ float tanh_approx(float x) {
    float y;
    asm("tanh.approx.f32 %0, %1;" : "=f"(y) : "f"(x));
    return y;
}

// Second half of spu given precomputed tanh(x/2).
__device__ __forceinline__ float spu_sel(float x, float t) {
    float p = fmaf(x, x, -0.5f);
    float n = fmaf(-0.5f, t, -0.5f);   // sigmoid(-x) - 1
    return (x >= 0.0f) ? p : n;
}

// Row tail: everything after vl/vu and the (u-l) reciprocal are known.
__device__ __forceinline__ float2 spu_tail(float l, float u,
                                           float vl, float vu, float rdiff,
                                           float ls_l, float ls_u,
                                           float lsh_l, float lsh_u,
                                           float lb_l, float lb_u) {
    bool neg   = (u <= 0.0f);
    bool pos   = (l >= 0.0f);
    bool cross = !(neg || pos);

    float all_slopes = (vu - vl) * rdiff;
    float slope_u = (pos || cross) ? all_slopes : 0.0f;
    float slope_l = neg ? all_slopes : 0.0f;

    bool sw = (all_slopes < 0.0f);
    float v_l = sw ? vu : vl;
    float v_u = sw ? vl : vu;
    float b_l = sw ? u : l;
    float b_u = sw ? l : u;

    float bnd_l = cross ? -0.5f : v_l;
    float bnd_u = v_u;

    float shift_u = fmaf(-slope_u, b_u, v_u);
    float shift_l = cross ? -0.5f : fmaf(-slope_l, b_l, v_l);

    float Ud = slope_u * ls_u;
    float UV = fmaf(slope_u, lsh_u, shift_u);
    float Ld = slope_l * ls_l;
    float LV = fmaf(slope_l, lsh_l, shift_l);

    float lb = fmaf(fmaxf(Ld, 0.0f), lb_l, fmaf(fminf(Ld, 0.0f), lb_u, LV));
    float ub = fmaf(fmaxf(Ud, 0.0f), lb_u, fmaf(fminf(Ud, 0.0f), lb_l, UV));

    return make_float2(fmaxf(lb, bnd_l), fminf(ub, bnd_u));
}

__global__ void __launch_bounds__(128, 1) spu_transformer_exact(
    const float4* __restrict__ bounds,
    const float4* __restrict__ last_slopes,
    const float4* __restrict__ last_shifts,
    const float4* __restrict__ last_bounds,
    float4* __restrict__ out)
{
    int i = blockIdx.x * blockDim.x + threadIdx.x;

    // 4 front-batched LDG.128 (MLP=4).
    float4 b   = bounds[i];
    float4 ls  = last_slopes[i];
    float4 lsh = last_shifts[i];
    float4 lb2 = last_bounds[i];

    // Batch all 4 MUFU.TANH + 2 MUFU.RCP so their latencies overlap.
    float t0 = tanh_approx(0.5f * b.x);
    float t1 = tanh_approx(0.5f * b.y);
    float t2 = tanh_approx(0.5f * b.z);
    float t3 = tanh_approx(0.5f * b.w);
    float rd0 = __frcp_rn(b.y - b.x);   // note: rn rcp; see below
    float rd1 = __frcp_rn(b.w - b.z);

    float vl0 = spu_sel(b.x, t0);
    float vu0 = spu_sel(b.y, t1);
    float vl1 = spu_sel(b.z, t2);
    float vu1 = spu_sel(b.w, t3);

    float2 r0 = spu_tail(b.x, b.y, vl0, vu0, rd0,
                         ls.x, ls.y, lsh.x, lsh.y, lb2.x, lb2.y);
    float2 r1 = spu_tail(b.z, b.w, vl1, vu1, rd1,
                         ls.z, ls.w, lsh.z, lsh.w, lb2.z, lb2.w);

    out[i] = make_float4(r0.x, r0.y, r1.x, r1.y);
}

__global__ void __launch_bounds__(128, 1) spu_transformer_guard(
    const float4* __restrict__ bounds,
    const float4* __restrict__ last_slopes,
    const float4* __restrict__ last_shifts,
    const float4* __restrict__ last_bounds,
    float4* __restrict__ out,
    int n4)
{
    int i = blockIdx.x * blockDim.x + threadIdx.x;
    if (i < n4) {
        float4 b   = bounds[i];
        float4 ls  = last_slopes[i];
        float4 lsh = last_shifts[i];
        float4 lb2 = last_bounds[i];

        float t0 = tanh_approx(0.5f * b.x);
        float t1 = tanh_approx(0.5f * b.y);
        float t2 = tanh_approx(0.5f * b.z);
        float t3 = tanh_approx(0.5f * b.w);
        float rd0 = __frcp_rn(b.y - b.x);
        float rd1 = __frcp_rn(b.w - b.z);

        float vl0 = spu_sel(b.x, t0);
        float vu0 = spu_sel(b.y, t1);
        float vl1 = spu_sel(b.z, t2);
        float vu1 = spu_sel(b.w, t3);

        float2 r0 = spu_tail(b.x, b.y, vl0, vu0, rd0,
                             ls.x, ls.y, lsh.x, lsh.y, lb2.x, lb2.y);
        float2 r1 = spu_tail(b.z, b.w, vl1, vu1, rd1,
                             ls.z, ls.w, lsh.z, lsh.w, lb2.z, lb2.w);

        out[i] = make_float4(r0.x, r0.y, r1.x, r1.y);
    }
}

extern "C" void kernel_launch(void* const* d_in, const int* in_sizes, int n_in,
                              void* d_out, int out_size) {
    const float4* bounds      = (const float4*)d_in[0];
    const float4* last_slopes = (const float4*)d_in[1];
    const float4* last_shifts = (const float4*)d_in[2];
    const float4* last_bounds = (const float4*)d_in[3];
    float4* out = (float4*)d_out;

    int n4 = in_sizes[0] / 4;            // 8192*2 floats -> 4096 float4
    const int threads = 128;
    if ((n4 % threads) == 0) {
        spu_transformer_exact<<<n4 / threads, threads>>>(
            bounds, last_slopes, last_shifts, last_bounds, out);
    } else {
        spu_transformer_guard<<<(n4 + threads - 1) / threads, threads>>>(
            bounds, last_slopes, last_shifts, last_bounds, out, n4);
    }
}